// round 7
// baseline (speedup 1.0000x reference)
#include <cuda_runtime.h>
#include <math.h>

#define BB   2
#define LL   2048
#define NRES 4096
#define KNB  48
#define NIN  416     // 16 pos + 25*16 rbf
#define NOUT 128
#define EPITCH 132   // padded Esh pitch

// smem layout (float offsets)
#define SM_FT   0        // ftile[2][16*48]   = 1536
#define SM_WS   1536     // Wsh[2][16*128]    = 4096
#define SM_DS   5632     // dsh[25*48]        = 1200
#define SM_XJ   6832     // xj[48*15]         = 720
#define SM_XI   7552     // xi[16]
#define SM_JN   7568     // jn[48] (int)
#define SM_OFF  7616     // offp[48] (int)
#define SM_TOT  7664

typedef unsigned long long ull;

// scratch (no allocations allowed)
__device__ float g_Xall[NRES * 15];     // 5 atoms x 3 per residue
__device__ int   g_Eidx[NRES * KNB];

__device__ __forceinline__ ull fma2(ull a, ull b, ull c) {
    ull d;
    asm("fma.rn.f32x2 %0, %1, %2, %3;" : "=l"(d) : "l"(a), "l"(b), "l"(c));
    return d;
}
__device__ __forceinline__ ull pack2(float f) {
    ull p;
    asm("mov.b64 %0, {%1, %1};" : "=l"(p) : "r"(__float_as_uint(f)));
    return p;
}
__device__ __forceinline__ float2 unpack2(ull v) {
    unsigned lo, hi;
    asm("mov.b64 {%0, %1}, %2;" : "=r"(lo), "=r"(hi) : "l"(v));
    float2 r; r.x = __uint_as_float(lo); r.y = __uint_as_float(hi);
    return r;
}

// ---------------------------------------------------------------------------
// Kernel 1: gather backbone atoms, build virtual atom
// ---------------------------------------------------------------------------
__global__ void build_xall_kernel(const float* __restrict__ X,
                                  const int* __restrict__ S,
                                  const int* __restrict__ table) {
    int g = blockIdx.x * blockDim.x + threadIdx.x;
    if (g >= NRES) return;
    int s = S[g];
    const float* Xr = X + (size_t)g * 14 * 3;
    float bb[12];
#pragma unroll
    for (int a = 0; a < 4; a++) {
        int ai = table[s * 4 + a];
        bb[a * 3 + 0] = Xr[ai * 3 + 0];
        bb[a * 3 + 1] = Xr[ai * 3 + 1];
        bb[a * 3 + 2] = Xr[ai * 3 + 2];
    }
    float b1x = bb[0] - bb[3], b1y = bb[1] - bb[4], b1z = bb[2] - bb[5];
    float b2x = bb[6] - bb[3], b2y = bb[7] - bb[4], b2z = bb[8] - bb[5];
    float nx = b1y * b2z - b1z * b2y;
    float ny = b1z * b2x - b1x * b2z;
    float nz = b1x * b2y - b1y * b2x;
    const float wN = 0.58273431f, w1 = -0.56802827f, w2 = -0.54067466f;
    float vx = wN * nx + w1 * b1x + w2 * b2x + bb[3];
    float vy = wN * ny + w1 * b1y + w2 * b2y + bb[4];
    float vz = wN * nz + w1 * b1z + w2 * b2z + bb[5];
    float* o = g_Xall + g * 15;
#pragma unroll
    for (int t = 0; t < 12; t++) o[t] = bb[t];
    o[12] = vx; o[13] = vy; o[14] = vz;
}

// ---------------------------------------------------------------------------
// Kernel 2: top-48 by 2-level radix select on float bits (monotone for d>0).
// ---------------------------------------------------------------------------
__global__ void topk_kernel(float* __restrict__ outEidxF, int write_idx_out) {
    __shared__ unsigned ud[LL];          // distance bits
    __shared__ int      hist[256];
    __shared__ unsigned cand_u[LL];
    __shared__ int      cand_i[LL];
    __shared__ unsigned sel_u[KNB];
    __shared__ int      sel_i[KNB];
    __shared__ int s_E, s_cA, s_M, s_c0, s_nsel, s_ncand;

    int row = blockIdx.x;
    int b = row / LL;
    int tid = threadIdx.x;

    const float* ca_i = g_Xall + row * 15 + 3;
    float cx = ca_i[0], cy = ca_i[1], cz = ca_i[2];
    for (int j = tid; j < LL; j += 256) {
        const float* cj = g_Xall + (b * LL + j) * 15 + 3;
        float dx = cx - cj[0], dy = cy - cj[1], dz = cz - cj[2];
        float d = sqrtf(dx * dx + dy * dy + dz * dz + 1e-6f);
        ud[j] = __float_as_uint(d);
    }
    hist[tid] = 0;
    if (tid == 0) { s_nsel = 0; s_ncand = 0; }
    __syncthreads();

    for (int j = tid; j < LL; j += 256) atomicAdd(&hist[ud[j] >> 23], 1);
    __syncthreads();
    if (tid < 32) {
        int base = tid * 8, loc[8], s = 0;
#pragma unroll
        for (int k = 0; k < 8; k++) { loc[k] = hist[base + k]; s += loc[k]; }
        int pre = s;
#pragma unroll
        for (int o = 1; o < 32; o <<= 1) {
            int v = __shfl_up_sync(0xffffffffu, pre, o);
            if (tid >= o) pre += v;
        }
        int excl = pre - s;
        if (excl < KNB && pre >= KNB) {
            int c = excl;
#pragma unroll
            for (int k = 0; k < 8; k++) {
                if (c + loc[k] >= KNB) { s_E = base + k; s_cA = c; break; }
                c += loc[k];
            }
        }
    }
    __syncthreads();
    int E = s_E, cA = s_cA, target2 = KNB - cA;
    hist[tid] = 0;
    __syncthreads();

    for (int j = tid; j < LL; j += 256) {
        unsigned u = ud[j];
        if ((int)(u >> 23) == E) atomicAdd(&hist[(u >> 15) & 0xFF], 1);
    }
    __syncthreads();
    if (tid < 32) {
        int base = tid * 8, loc[8], s = 0;
#pragma unroll
        for (int k = 0; k < 8; k++) { loc[k] = hist[base + k]; s += loc[k]; }
        int pre = s;
#pragma unroll
        for (int o = 1; o < 32; o <<= 1) {
            int v = __shfl_up_sync(0xffffffffu, pre, o);
            if (tid >= o) pre += v;
        }
        int excl = pre - s;
        if (excl < target2 && pre >= target2) {
            int c = excl;
#pragma unroll
            for (int k = 0; k < 8; k++) {
                if (c + loc[k] >= target2) { s_M = base + k; s_c0 = cA + c; break; }
                c += loc[k];
            }
        }
    }
    __syncthreads();
    unsigned T17 = ((unsigned)E << 8) | (unsigned)s_M;
    int c0 = s_c0;

    for (int j = tid; j < LL; j += 256) {
        unsigned u = ud[j], k17 = u >> 15;
        if (k17 < T17) {
            int p = atomicAdd(&s_nsel, 1);
            sel_u[p] = u; sel_i[p] = j;
        } else if (k17 == T17) {
            int p = atomicAdd(&s_ncand, 1);
            cand_u[p] = u; cand_i[p] = j;
        }
    }
    __syncthreads();

    int need = KNB - c0;
    int s = s_ncand;
    for (int c = tid; c < s; c += 256) {
        unsigned u = cand_u[c]; int i = cand_i[c]; int r = 0;
        for (int c2 = 0; c2 < s; c2++) {
            unsigned u2 = cand_u[c2]; int i2 = cand_i[c2];
            if (u2 < u || (u2 == u && i2 < i)) r++;
        }
        if (r < need) { sel_u[c0 + r] = u; sel_i[c0 + r] = i; }
    }
    __syncthreads();

    for (int t = tid; t < KNB; t += 256) {
        if (t < c0) {
            unsigned u = sel_u[t]; int i = sel_i[t]; int r = 0;
            for (int t2 = 0; t2 < c0; t2++) {
                unsigned u2 = sel_u[t2]; int i2 = sel_i[t2];
                if (u2 < u || (u2 == u && i2 < i)) r++;
            }
            g_Eidx[row * KNB + r] = i;
            if (write_idx_out) outEidxF[(size_t)row * KNB + r] = (float)i;
        } else {
            int i = sel_i[t];
            g_Eidx[row * KNB + t] = i;
            if (write_idx_out) outEidxF[(size_t)row * KNB + t] = (float)i;
        }
    }
}

// ---------------------------------------------------------------------------
// Kernel 3: pipelined on-the-fly features + FFMA2 GEMM (416->128) + LN.
// K-tiles of 16 rows, double-buffered ftile/Wsh, 5 blocks/SM.
// ---------------------------------------------------------------------------
__global__ __launch_bounds__(128, 5)
void edge_kernel(const int* __restrict__ residue_idx,
                 const float* __restrict__ W_pos, const float* __restrict__ b_pos,
                 const float* __restrict__ W_e,
                 const float* __restrict__ ln_g, const float* __restrict__ ln_b,
                 float* __restrict__ outE) {
    extern __shared__ float sm[];
    float* ftile = sm + SM_FT;     // [2][16*48]
    float* Wsh   = sm + SM_WS;     // [2][16*128]
    float* dsh   = sm + SM_DS;     // [25][48]
    float* xj    = sm + SM_XJ;     // [48][15]
    float* xi    = sm + SM_XI;     // [16]
    int*   jn    = (int*)(sm + SM_JN);
    int*   offp  = (int*)(sm + SM_OFF);

    int row = blockIdx.x;
    int b = row / LL;
    int tid = threadIdx.x;

    if (tid < 15) xi[tid] = g_Xall[row * 15 + tid];
    if (tid < KNB) {
        int j = g_Eidx[row * KNB + tid];
        jn[tid] = j;
        int d = residue_idx[row] - residue_idx[b * LL + j] + 32;
        d = min(max(d, 0), 64);
        offp[tid] = d;
    }
    __syncthreads();

    for (int t = tid; t < KNB * 15; t += 128) {
        int e = t / 15, cmp = t % 15;
        xj[t] = g_Xall[(b * LL + jn[e]) * 15 + cmp];
    }
    __syncthreads();

    // distance table dsh[p*48+e], p = a*5+c
    for (int t = tid; t < 25 * KNB; t += 128) {
        int e = t % KNB, p = t / KNB;
        int a = p / 5, c = p % 5;
        float dx = xi[a * 3 + 0] - xj[e * 15 + c * 3 + 0];
        float dy = xi[a * 3 + 1] - xj[e * 15 + c * 3 + 1];
        float dz = xi[a * 3 + 2] - xj[e * 15 + c * 3 + 2];
        dsh[t] = sqrtf(dx * dx + dy * dy + dz * dz + 1e-6f);
    }

    // prologue: fill buffer 0 with tile 0 (positional rows f=0..15) + W rows
    {
        const float4* src = (const float4*)W_e;
        float4* dst4 = (float4*)Wsh;
        for (int t = tid; t < 16 * 128 / 4; t += 128) dst4[t] = src[t];
    }
    __syncthreads();   // dsh ready (needed by iter-0 fill of tile 1)
#pragma unroll
    for (int k = 0; k < 6; k++) {
        int idx = tid + k * 128;           // 768 = 16*48
        int e = idx % KNB, f = idx / KNB;
        ftile[idx] = W_pos[offp[e] * 16 + f] + b_pos[f];
    }

    int tx = tid >> 3, te = tid & 7;
    ull acc[24];
#pragma unroll
    for (int q = 0; q < 24; q++) acc[q] = 0ull;

    const float inv_sig = 1.0f / 1.25f;

    for (int t = 0; t < 26; t++) {
        __syncthreads();   // buffer t&1 filled; buffer (t+1)&1 free
        int buf = t & 1, nb = buf ^ 1;

        if (t < 25) {
            // fill next W tile (rows (t+1)*16 .. +16)
            const float4* src = (const float4*)(W_e + (t + 1) * 16 * 128);
            float4* dst4 = (float4*)(Wsh + nb * 2048);
            for (int q = tid; q < 16 * 128 / 4; q += 128) dst4[q] = src[q];
            // fill next feature tile: RBF group p = t, rows m=0..15
            float* fdst = ftile + nb * 768;
            const float* drow = dsh + t * KNB;
#pragma unroll
            for (int k = 0; k < 6; k++) {
                int idx = tid + k * 128;
                int e = idx % KNB, m = idx / KNB;
                float d = drow[e];
                float mu = 2.0f + (float)m * (20.0f / 15.0f);
                float z = (d - mu) * inv_sig;
                fdst[idx] = __expf(-z * z);
            }
        }

        const ull* Wu = (const ull*)(Wsh + buf * 2048);
        const float* fb = ftile + buf * 768;
#pragma unroll
        for (int ff = 0; ff < 16; ff++) {
            ull w0 = Wu[ff * 64 + tx];
            ull w1 = Wu[ff * 64 + tx + 16];
            ull w2 = Wu[ff * 64 + tx + 32];
            ull w3 = Wu[ff * 64 + tx + 48];
            const ull* fu = (const ull*)(fb + ff * KNB) + te * 3;
            float2 f01 = unpack2(fu[0]);
            float2 f23 = unpack2(fu[1]);
            float2 f45 = unpack2(fu[2]);
            ull p0 = pack2(f01.x), p1 = pack2(f01.y);
            ull p2 = pack2(f23.x), p3 = pack2(f23.y);
            ull p4 = pack2(f45.x), p5 = pack2(f45.y);
            acc[0]  = fma2(w0, p0, acc[0]);
            acc[1]  = fma2(w1, p0, acc[1]);
            acc[2]  = fma2(w2, p0, acc[2]);
            acc[3]  = fma2(w3, p0, acc[3]);
            acc[4]  = fma2(w0, p1, acc[4]);
            acc[5]  = fma2(w1, p1, acc[5]);
            acc[6]  = fma2(w2, p1, acc[6]);
            acc[7]  = fma2(w3, p1, acc[7]);
            acc[8]  = fma2(w0, p2, acc[8]);
            acc[9]  = fma2(w1, p2, acc[9]);
            acc[10] = fma2(w2, p2, acc[10]);
            acc[11] = fma2(w3, p2, acc[11]);
            acc[12] = fma2(w0, p3, acc[12]);
            acc[13] = fma2(w1, p3, acc[13]);
            acc[14] = fma2(w2, p3, acc[14]);
            acc[15] = fma2(w3, p3, acc[15]);
            acc[16] = fma2(w0, p4, acc[16]);
            acc[17] = fma2(w1, p4, acc[17]);
            acc[18] = fma2(w2, p4, acc[18]);
            acc[19] = fma2(w3, p4, acc[19]);
            acc[20] = fma2(w0, p5, acc[20]);
            acc[21] = fma2(w1, p5, acc[21]);
            acc[22] = fma2(w2, p5, acc[22]);
            acc[23] = fma2(w3, p5, acc[23]);
        }
    }
    __syncthreads();       // all reads done; reuse smem base as E staging

    float* Esh = sm;       // [48][EPITCH]  (6336 floats <= SM_TOT)
#pragma unroll
    for (int e = 0; e < 6; e++) {
        int edge = te * 6 + e;
#pragma unroll
        for (int p = 0; p < 4; p++) {
            float2 c = unpack2(acc[e * 4 + p]);
            *(float2*)(Esh + edge * EPITCH + (tx + 16 * p) * 2) = c;
        }
    }
    __syncthreads();

    // LayerNorm: warp w handles edges w*12 .. w*12+11
    int w = tid >> 5, lane = tid & 31;
    for (int e = w * 12; e < w * 12 + 12; e++) {
        float v0 = Esh[e * EPITCH + lane];
        float v1 = Esh[e * EPITCH + lane + 32];
        float v2 = Esh[e * EPITCH + lane + 64];
        float v3 = Esh[e * EPITCH + lane + 96];
        float s  = v0 + v1 + v2 + v3;
        float ss = v0 * v0 + v1 * v1 + v2 * v2 + v3 * v3;
#pragma unroll
        for (int o = 16; o > 0; o >>= 1) {
            s  += __shfl_xor_sync(0xffffffffu, s, o);
            ss += __shfl_xor_sync(0xffffffffu, ss, o);
        }
        float mean = s * (1.0f / 128.0f);
        float var  = ss * (1.0f / 128.0f) - mean * mean;
        float rstd = rsqrtf(var + 1e-5f);
        size_t base = ((size_t)row * KNB + e) * 128;
        outE[base + lane]      = (v0 - mean) * rstd * ln_g[lane]      + ln_b[lane];
        outE[base + lane + 32] = (v1 - mean) * rstd * ln_g[lane + 32] + ln_b[lane + 32];
        outE[base + lane + 64] = (v2 - mean) * rstd * ln_g[lane + 64] + ln_b[lane + 64];
        outE[base + lane + 96] = (v3 - mean) * rstd * ln_g[lane + 96] + ln_b[lane + 96];
    }
}

// ---------------------------------------------------------------------------
extern "C" void kernel_launch(void* const* d_in, const int* in_sizes, int n_in,
                              void* d_out, int out_size) {
    const float* X     = (const float*)d_in[0];
    const int*   S     = (const int*)d_in[2];
    const int*   ridx  = (const int*)d_in[3];
    const int*   table = (const int*)d_in[5];
    const float* W_pos = (const float*)d_in[6];
    const float* b_pos = (const float*)d_in[7];
    const float* W_e   = (const float*)d_in[8];
    const float* ln_g  = (const float*)d_in[9];
    const float* ln_b  = (const float*)d_in[10];
    float* out = (float*)d_out;

    const size_t E_elems = (size_t)NRES * KNB * NOUT;       // 25,165,824
    int write_idx = (out_size >= (int)(E_elems + (size_t)NRES * KNB)) ? 1 : 0;

    build_xall_kernel<<<(NRES + 255) / 256, 256>>>(X, S, table);
    topk_kernel<<<NRES, 256>>>(out + E_elems, write_idx);

    size_t smem = (size_t)SM_TOT * sizeof(float);
    cudaFuncSetAttribute(edge_kernel, cudaFuncAttributeMaxDynamicSharedMemorySize, (int)smem);
    edge_kernel<<<NRES, 128, smem>>>(ridx, W_pos, b_pos, W_e, ln_g, ln_b, out);
}

// round 8
// speedup vs baseline: 1.0382x; 1.0382x over previous
#include <cuda_runtime.h>
#include <math.h>

#define BB   2
#define LL   2048
#define NRES 4096
#define KNB  48
#define NIN  416     // 16 pos + 25*16 rbf
#define NOUT 128
#define EPITCH 132   // padded Esh pitch

typedef unsigned long long ull;

// scratch (no allocations allowed)
__device__ float g_Xall[NRES * 15];     // 5 atoms x 3 per residue
__device__ int   g_Eidx[NRES * KNB];

__device__ __forceinline__ ull fma2(ull a, ull b, ull c) {
    ull d;
    asm("fma.rn.f32x2 %0, %1, %2, %3;" : "=l"(d) : "l"(a), "l"(b), "l"(c));
    return d;
}
__device__ __forceinline__ ull pack2(float f) {
    ull p;
    asm("mov.b64 %0, {%1, %1};" : "=l"(p) : "r"(__float_as_uint(f)));
    return p;
}
__device__ __forceinline__ float2 unpack2(ull v) {
    unsigned lo, hi;
    asm("mov.b64 {%0, %1}, %2;" : "=r"(lo), "=r"(hi) : "l"(v));
    float2 r; r.x = __uint_as_float(lo); r.y = __uint_as_float(hi);
    return r;
}

// ---------------------------------------------------------------------------
// Kernel 1: gather backbone atoms, build virtual atom
// ---------------------------------------------------------------------------
__global__ void build_xall_kernel(const float* __restrict__ X,
                                  const int* __restrict__ S,
                                  const int* __restrict__ table) {
    int g = blockIdx.x * blockDim.x + threadIdx.x;
    if (g >= NRES) return;
    int s = S[g];
    const float* Xr = X + (size_t)g * 14 * 3;
    float bb[12];
#pragma unroll
    for (int a = 0; a < 4; a++) {
        int ai = table[s * 4 + a];
        bb[a * 3 + 0] = Xr[ai * 3 + 0];
        bb[a * 3 + 1] = Xr[ai * 3 + 1];
        bb[a * 3 + 2] = Xr[ai * 3 + 2];
    }
    float b1x = bb[0] - bb[3], b1y = bb[1] - bb[4], b1z = bb[2] - bb[5];
    float b2x = bb[6] - bb[3], b2y = bb[7] - bb[4], b2z = bb[8] - bb[5];
    float nx = b1y * b2z - b1z * b2y;
    float ny = b1z * b2x - b1x * b2z;
    float nz = b1x * b2y - b1y * b2x;
    const float wN = 0.58273431f, w1 = -0.56802827f, w2 = -0.54067466f;
    float vx = wN * nx + w1 * b1x + w2 * b2x + bb[3];
    float vy = wN * ny + w1 * b1y + w2 * b2y + bb[4];
    float vz = wN * nz + w1 * b1z + w2 * b2z + bb[5];
    float* o = g_Xall + g * 15;
#pragma unroll
    for (int t = 0; t < 12; t++) o[t] = bb[t];
    o[12] = vx; o[13] = vy; o[14] = vz;
}

// ---------------------------------------------------------------------------
// Kernel 2: top-48 by 2-level radix select on float bits (monotone for d>0).
// ---------------------------------------------------------------------------
__global__ void topk_kernel(float* __restrict__ outEidxF, int write_idx_out) {
    __shared__ unsigned ud[LL];          // distance bits
    __shared__ int      hist[256];
    __shared__ unsigned cand_u[LL];
    __shared__ int      cand_i[LL];
    __shared__ unsigned sel_u[KNB];
    __shared__ int      sel_i[KNB];
    __shared__ int s_E, s_cA, s_M, s_c0, s_nsel, s_ncand;

    int row = blockIdx.x;
    int b = row / LL;
    int tid = threadIdx.x;

    const float* ca_i = g_Xall + row * 15 + 3;
    float cx = ca_i[0], cy = ca_i[1], cz = ca_i[2];
    for (int j = tid; j < LL; j += 256) {
        const float* cj = g_Xall + (b * LL + j) * 15 + 3;
        float dx = cx - cj[0], dy = cy - cj[1], dz = cz - cj[2];
        float d = sqrtf(dx * dx + dy * dy + dz * dz + 1e-6f);
        ud[j] = __float_as_uint(d);
    }
    hist[tid] = 0;
    if (tid == 0) { s_nsel = 0; s_ncand = 0; }
    __syncthreads();

    for (int j = tid; j < LL; j += 256) atomicAdd(&hist[ud[j] >> 23], 1);
    __syncthreads();
    if (tid < 32) {
        int base = tid * 8, loc[8], s = 0;
#pragma unroll
        for (int k = 0; k < 8; k++) { loc[k] = hist[base + k]; s += loc[k]; }
        int pre = s;
#pragma unroll
        for (int o = 1; o < 32; o <<= 1) {
            int v = __shfl_up_sync(0xffffffffu, pre, o);
            if (tid >= o) pre += v;
        }
        int excl = pre - s;
        if (excl < KNB && pre >= KNB) {
            int c = excl;
#pragma unroll
            for (int k = 0; k < 8; k++) {
                if (c + loc[k] >= KNB) { s_E = base + k; s_cA = c; break; }
                c += loc[k];
            }
        }
    }
    __syncthreads();
    int E = s_E, cA = s_cA, target2 = KNB - cA;
    hist[tid] = 0;
    __syncthreads();

    for (int j = tid; j < LL; j += 256) {
        unsigned u = ud[j];
        if ((int)(u >> 23) == E) atomicAdd(&hist[(u >> 15) & 0xFF], 1);
    }
    __syncthreads();
    if (tid < 32) {
        int base = tid * 8, loc[8], s = 0;
#pragma unroll
        for (int k = 0; k < 8; k++) { loc[k] = hist[base + k]; s += loc[k]; }
        int pre = s;
#pragma unroll
        for (int o = 1; o < 32; o <<= 1) {
            int v = __shfl_up_sync(0xffffffffu, pre, o);
            if (tid >= o) pre += v;
        }
        int excl = pre - s;
        if (excl < target2 && pre >= target2) {
            int c = excl;
#pragma unroll
            for (int k = 0; k < 8; k++) {
                if (c + loc[k] >= target2) { s_M = base + k; s_c0 = cA + c; break; }
                c += loc[k];
            }
        }
    }
    __syncthreads();
    unsigned T17 = ((unsigned)E << 8) | (unsigned)s_M;
    int c0 = s_c0;

    for (int j = tid; j < LL; j += 256) {
        unsigned u = ud[j], k17 = u >> 15;
        if (k17 < T17) {
            int p = atomicAdd(&s_nsel, 1);
            sel_u[p] = u; sel_i[p] = j;
        } else if (k17 == T17) {
            int p = atomicAdd(&s_ncand, 1);
            cand_u[p] = u; cand_i[p] = j;
        }
    }
    __syncthreads();

    int need = KNB - c0;
    int s = s_ncand;
    for (int c = tid; c < s; c += 256) {
        unsigned u = cand_u[c]; int i = cand_i[c]; int r = 0;
        for (int c2 = 0; c2 < s; c2++) {
            unsigned u2 = cand_u[c2]; int i2 = cand_i[c2];
            if (u2 < u || (u2 == u && i2 < i)) r++;
        }
        if (r < need) { sel_u[c0 + r] = u; sel_i[c0 + r] = i; }
    }
    __syncthreads();

    for (int t = tid; t < KNB; t += 256) {
        if (t < c0) {
            unsigned u = sel_u[t]; int i = sel_i[t]; int r = 0;
            for (int t2 = 0; t2 < c0; t2++) {
                unsigned u2 = sel_u[t2]; int i2 = sel_i[t2];
                if (u2 < u || (u2 == u && i2 < i)) r++;
            }
            g_Eidx[row * KNB + r] = i;
            if (write_idx_out) outEidxF[(size_t)row * KNB + r] = (float)i;
        } else {
            int i = sel_i[t];
            g_Eidx[row * KNB + t] = i;
            if (write_idx_out) outEidxF[(size_t)row * KNB + t] = (float)i;
        }
    }
}

// ---------------------------------------------------------------------------
// Kernel 3: fused features + GEMM (416->128) + LN.
// 256 threads: tx = tid&15 owns channel-pairs {tx,tx+16,tx+32,tx+48}
// (channels 2q,2q+1); te = tid>>4 owns edges te*3..te*3+2. 12 f32x2 accs.
// ---------------------------------------------------------------------------
__global__ __launch_bounds__(256, 2)
void edge_kernel(const int* __restrict__ residue_idx,
                 const float* __restrict__ W_pos, const float* __restrict__ b_pos,
                 const float* __restrict__ W_e,
                 const float* __restrict__ ln_g, const float* __restrict__ ln_b,
                 float* __restrict__ outE) {
    extern __shared__ float sm[];
    float* featT = sm;                       // [416][48]
    float* Wsh   = sm + NIN * KNB;           // [32][128] row-major
    float* xj    = Wsh + 32 * 128;           // [48][15]
    float* xi    = xj + KNB * 15;            // [15] (+1 pad)
    int*   jn    = (int*)(xi + 16);          // [48]
    int*   offp  = jn + KNB;                 // [48]

    int row = blockIdx.x;
    int b = row / LL;
    int tid = threadIdx.x;

    if (tid < 15) xi[tid] = g_Xall[row * 15 + tid];
    if (tid < KNB) {
        int j = g_Eidx[row * KNB + tid];
        jn[tid] = j;
        int d = residue_idx[row] - residue_idx[b * LL + j] + 32;
        d = min(max(d, 0), 64);
        offp[tid] = d;
    }
    __syncthreads();

    for (int t = tid; t < KNB * 15; t += 256) {
        int e = t / 15, cmp = t % 15;
        xj[t] = g_Xall[(b * LL + jn[e]) * 15 + cmp];
    }
    // positional features: feat[0..15]
    for (int t = tid; t < KNB * 16; t += 256) {
        int e = t % KNB, c = t / KNB;
        featT[c * KNB + e] = W_pos[offp[e] * 16 + c] + b_pos[c];
    }
    __syncthreads();

    // RBF features: feat[16 + (a*5+c)*16 + m]
    const float inv_sig = 1.0f / 1.25f;
    for (int t = tid; t < KNB * 25; t += 256) {
        int e = t % KNB, p = t / KNB;
        int a = p / 5, c = p % 5;
        float dx = xi[a * 3 + 0] - xj[e * 15 + c * 3 + 0];
        float dy = xi[a * 3 + 1] - xj[e * 15 + c * 3 + 1];
        float dz = xi[a * 3 + 2] - xj[e * 15 + c * 3 + 2];
        float d = sqrtf(dx * dx + dy * dy + dz * dz + 1e-6f);
        float* dst = featT + (16 + p * 16) * KNB + e;
#pragma unroll
        for (int m = 0; m < 16; m++) {
            float mu = 2.0f + (float)m * (20.0f / 15.0f);
            float z = (d - mu) * inv_sig;
            dst[m * KNB] = __expf(-z * z);
        }
    }

    int tx = tid & 15, te = tid >> 4;
    int e3 = te * 3;
    ull acc[12];
#pragma unroll
    for (int q = 0; q < 12; q++) acc[q] = 0ull;

    const ull* Wu = (const ull*)Wsh;

    for (int f0 = 0; f0 < NIN; f0 += 32) {
        __syncthreads();   // prev tile consumed; orders featT writes on iter 0
        {
            const float4* src = (const float4*)(W_e + f0 * 128);
            float4* dst4 = (float4*)Wsh;
            for (int t = tid; t < 32 * 128 / 4; t += 256) dst4[t] = src[t];
        }
        __syncthreads();
#pragma unroll 8
        for (int ff = 0; ff < 32; ff++) {
            // 4 conflict-free LDS.64 (16 distinct addrs/warp, 8B apart)
            ull w0 = Wu[ff * 64 + tx];
            ull w1 = Wu[ff * 64 + tx + 16];
            ull w2 = Wu[ff * 64 + tx + 32];
            ull w3 = Wu[ff * 64 + tx + 48];
            // 3 scalar feat loads (2 distinct addrs/warp -> broadcast)
            const float* frow = featT + (f0 + ff) * KNB + e3;
            ull p0 = pack2(frow[0]);
            ull p1 = pack2(frow[1]);
            ull p2 = pack2(frow[2]);
            acc[0]  = fma2(w0, p0, acc[0]);
            acc[1]  = fma2(w1, p0, acc[1]);
            acc[2]  = fma2(w2, p0, acc[2]);
            acc[3]  = fma2(w3, p0, acc[3]);
            acc[4]  = fma2(w0, p1, acc[4]);
            acc[5]  = fma2(w1, p1, acc[5]);
            acc[6]  = fma2(w2, p1, acc[6]);
            acc[7]  = fma2(w3, p1, acc[7]);
            acc[8]  = fma2(w0, p2, acc[8]);
            acc[9]  = fma2(w1, p2, acc[9]);
            acc[10] = fma2(w2, p2, acc[10]);
            acc[11] = fma2(w3, p2, acc[11]);
        }
    }
    __syncthreads();       // GEMM reads of featT done; reuse it as E staging

    float* Esh = featT;    // [48][EPITCH]
#pragma unroll
    for (int e = 0; e < 3; e++) {
        int edge = e3 + e;
#pragma unroll
        for (int p = 0; p < 4; p++) {
            float2 c = unpack2(acc[e * 4 + p]);
            *(float2*)(Esh + edge * EPITCH + (tx + 16 * p) * 2) = c;
        }
    }
    __syncthreads();

    // LayerNorm: warp w handles edges w*6 .. w*6+5
    int w = tid >> 5, lane = tid & 31;
    for (int e = w * 6; e < w * 6 + 6; e++) {
        float v0 = Esh[e * EPITCH + lane];
        float v1 = Esh[e * EPITCH + lane + 32];
        float v2 = Esh[e * EPITCH + lane + 64];
        float v3 = Esh[e * EPITCH + lane + 96];
        float s  = v0 + v1 + v2 + v3;
        float ss = v0 * v0 + v1 * v1 + v2 * v2 + v3 * v3;
#pragma unroll
        for (int o = 16; o > 0; o >>= 1) {
            s  += __shfl_xor_sync(0xffffffffu, s, o);
            ss += __shfl_xor_sync(0xffffffffu, ss, o);
        }
        float mean = s * (1.0f / 128.0f);
        float var  = ss * (1.0f / 128.0f) - mean * mean;
        float rstd = rsqrtf(var + 1e-5f);
        size_t base = ((size_t)row * KNB + e) * 128;
        outE[base + lane]      = (v0 - mean) * rstd * ln_g[lane]      + ln_b[lane];
        outE[base + lane + 32] = (v1 - mean) * rstd * ln_g[lane + 32] + ln_b[lane + 32];
        outE[base + lane + 64] = (v2 - mean) * rstd * ln_g[lane + 64] + ln_b[lane + 64];
        outE[base + lane + 96] = (v3 - mean) * rstd * ln_g[lane + 96] + ln_b[lane + 96];
    }
}

// ---------------------------------------------------------------------------
extern "C" void kernel_launch(void* const* d_in, const int* in_sizes, int n_in,
                              void* d_out, int out_size) {
    const float* X     = (const float*)d_in[0];
    const int*   S     = (const int*)d_in[2];
    const int*   ridx  = (const int*)d_in[3];
    const int*   table = (const int*)d_in[5];
    const float* W_pos = (const float*)d_in[6];
    const float* b_pos = (const float*)d_in[7];
    const float* W_e   = (const float*)d_in[8];
    const float* ln_g  = (const float*)d_in[9];
    const float* ln_b  = (const float*)d_in[10];
    float* out = (float*)d_out;

    const size_t E_elems = (size_t)NRES * KNB * NOUT;       // 25,165,824
    int write_idx = (out_size >= (int)(E_elems + (size_t)NRES * KNB)) ? 1 : 0;

    build_xall_kernel<<<(NRES + 255) / 256, 256>>>(X, S, table);
    topk_kernel<<<NRES, 256>>>(out + E_elems, write_idx);

    size_t smem = (size_t)(NIN * KNB + 32 * 128 + KNB * 15 + 16) * sizeof(float)
                + (size_t)(2 * KNB) * sizeof(int);
    cudaFuncSetAttribute(edge_kernel, cudaFuncAttributeMaxDynamicSharedMemorySize, (int)smem);
    edge_kernel<<<NRES, 256, smem>>>(ridx, W_pos, b_pos, W_e, ln_g, ln_b, out);
}

// round 9
// speedup vs baseline: 1.4218x; 1.3695x over previous
#include <cuda_runtime.h>
#include <math.h>

#define BB   2
#define LL   2048
#define NRES 4096
#define KNB  48
#define NIN  416     // 16 pos + 25*16 rbf
#define NOUT 128
#define EPITCH 132   // padded Esh pitch

typedef unsigned long long ull;

// scratch (no allocations allowed)
__device__ float g_Xall[NRES * 15];     // 5 atoms x 3 per residue
__device__ int   g_Eidx[NRES * KNB];

__device__ __forceinline__ ull fma2(ull a, ull b, ull c) {
    ull d;
    asm("fma.rn.f32x2 %0, %1, %2, %3;" : "=l"(d) : "l"(a), "l"(b), "l"(c));
    return d;
}
__device__ __forceinline__ ull pack2(float f) {
    ull p;
    asm("mov.b64 %0, {%1, %1};" : "=l"(p) : "r"(__float_as_uint(f)));
    return p;
}
__device__ __forceinline__ float2 unpack2(ull v) {
    unsigned lo, hi;
    asm("mov.b64 {%0, %1}, %2;" : "=r"(lo), "=r"(hi) : "l"(v));
    float2 r; r.x = __uint_as_float(lo); r.y = __uint_as_float(hi);
    return r;
}

// ---------------------------------------------------------------------------
// Kernel 1: gather backbone atoms, build virtual atom
// ---------------------------------------------------------------------------
__global__ void build_xall_kernel(const float* __restrict__ X,
                                  const int* __restrict__ S,
                                  const int* __restrict__ table) {
    int g = blockIdx.x * blockDim.x + threadIdx.x;
    if (g >= NRES) return;
    int s = S[g];
    const float* Xr = X + (size_t)g * 14 * 3;
    float bb[12];
#pragma unroll
    for (int a = 0; a < 4; a++) {
        int ai = table[s * 4 + a];
        bb[a * 3 + 0] = Xr[ai * 3 + 0];
        bb[a * 3 + 1] = Xr[ai * 3 + 1];
        bb[a * 3 + 2] = Xr[ai * 3 + 2];
    }
    float b1x = bb[0] - bb[3], b1y = bb[1] - bb[4], b1z = bb[2] - bb[5];
    float b2x = bb[6] - bb[3], b2y = bb[7] - bb[4], b2z = bb[8] - bb[5];
    float nx = b1y * b2z - b1z * b2y;
    float ny = b1z * b2x - b1x * b2z;
    float nz = b1x * b2y - b1y * b2x;
    const float wN = 0.58273431f, w1 = -0.56802827f, w2 = -0.54067466f;
    float vx = wN * nx + w1 * b1x + w2 * b2x + bb[3];
    float vy = wN * ny + w1 * b1y + w2 * b2y + bb[4];
    float vz = wN * nz + w1 * b1z + w2 * b2z + bb[5];
    float* o = g_Xall + g * 15;
#pragma unroll
    for (int t = 0; t < 12; t++) o[t] = bb[t];
    o[12] = vx; o[13] = vy; o[14] = vz;
}

// ---------------------------------------------------------------------------
// Kernel 2: top-48 by 2-level radix select on float bits (monotone for d>0).
// ---------------------------------------------------------------------------
__global__ void topk_kernel(float* __restrict__ outEidxF, int write_idx_out) {
    __shared__ unsigned ud[LL];          // distance bits
    __shared__ int      hist[256];
    __shared__ unsigned cand_u[LL];
    __shared__ int      cand_i[LL];
    __shared__ unsigned sel_u[KNB];
    __shared__ int      sel_i[KNB];
    __shared__ int s_E, s_cA, s_M, s_c0, s_nsel, s_ncand;

    int row = blockIdx.x;
    int b = row / LL;
    int tid = threadIdx.x;

    const float* ca_i = g_Xall + row * 15 + 3;
    float cx = ca_i[0], cy = ca_i[1], cz = ca_i[2];
    for (int j = tid; j < LL; j += 256) {
        const float* cj = g_Xall + (b * LL + j) * 15 + 3;
        float dx = cx - cj[0], dy = cy - cj[1], dz = cz - cj[2];
        float d = sqrtf(dx * dx + dy * dy + dz * dz + 1e-6f);
        ud[j] = __float_as_uint(d);
    }
    hist[tid] = 0;
    if (tid == 0) { s_nsel = 0; s_ncand = 0; }
    __syncthreads();

    for (int j = tid; j < LL; j += 256) atomicAdd(&hist[ud[j] >> 23], 1);
    __syncthreads();
    if (tid < 32) {
        int base = tid * 8, loc[8], s = 0;
#pragma unroll
        for (int k = 0; k < 8; k++) { loc[k] = hist[base + k]; s += loc[k]; }
        int pre = s;
#pragma unroll
        for (int o = 1; o < 32; o <<= 1) {
            int v = __shfl_up_sync(0xffffffffu, pre, o);
            if (tid >= o) pre += v;
        }
        int excl = pre - s;
        if (excl < KNB && pre >= KNB) {
            int c = excl;
#pragma unroll
            for (int k = 0; k < 8; k++) {
                if (c + loc[k] >= KNB) { s_E = base + k; s_cA = c; break; }
                c += loc[k];
            }
        }
    }
    __syncthreads();
    int E = s_E, cA = s_cA, target2 = KNB - cA;
    hist[tid] = 0;
    __syncthreads();

    for (int j = tid; j < LL; j += 256) {
        unsigned u = ud[j];
        if ((int)(u >> 23) == E) atomicAdd(&hist[(u >> 15) & 0xFF], 1);
    }
    __syncthreads();
    if (tid < 32) {
        int base = tid * 8, loc[8], s = 0;
#pragma unroll
        for (int k = 0; k < 8; k++) { loc[k] = hist[base + k]; s += loc[k]; }
        int pre = s;
#pragma unroll
        for (int o = 1; o < 32; o <<= 1) {
            int v = __shfl_up_sync(0xffffffffu, pre, o);
            if (tid >= o) pre += v;
        }
        int excl = pre - s;
        if (excl < target2 && pre >= target2) {
            int c = excl;
#pragma unroll
            for (int k = 0; k < 8; k++) {
                if (c + loc[k] >= target2) { s_M = base + k; s_c0 = cA + c; break; }
                c += loc[k];
            }
        }
    }
    __syncthreads();
    unsigned T17 = ((unsigned)E << 8) | (unsigned)s_M;
    int c0 = s_c0;

    for (int j = tid; j < LL; j += 256) {
        unsigned u = ud[j], k17 = u >> 15;
        if (k17 < T17) {
            int p = atomicAdd(&s_nsel, 1);
            sel_u[p] = u; sel_i[p] = j;
        } else if (k17 == T17) {
            int p = atomicAdd(&s_ncand, 1);
            cand_u[p] = u; cand_i[p] = j;
        }
    }
    __syncthreads();

    int need = KNB - c0;
    int s = s_ncand;
    for (int c = tid; c < s; c += 256) {
        unsigned u = cand_u[c]; int i = cand_i[c]; int r = 0;
        for (int c2 = 0; c2 < s; c2++) {
            unsigned u2 = cand_u[c2]; int i2 = cand_i[c2];
            if (u2 < u || (u2 == u && i2 < i)) r++;
        }
        if (r < need) { sel_u[c0 + r] = u; sel_i[c0 + r] = i; }
    }
    __syncthreads();

    for (int t = tid; t < KNB; t += 256) {
        if (t < c0) {
            unsigned u = sel_u[t]; int i = sel_i[t]; int r = 0;
            for (int t2 = 0; t2 < c0; t2++) {
                unsigned u2 = sel_u[t2]; int i2 = sel_i[t2];
                if (u2 < u || (u2 == u && i2 < i)) r++;
            }
            g_Eidx[row * KNB + r] = i;
            if (write_idx_out) outEidxF[(size_t)row * KNB + r] = (float)i;
        } else {
            int i = sel_i[t];
            g_Eidx[row * KNB + t] = i;
            if (write_idx_out) outEidxF[(size_t)row * KNB + t] = (float)i;
        }
    }
}

// ---------------------------------------------------------------------------
// Kernel 3: fused features + GEMM (416->128) + LN, conflict-free FFMA2 tile
// with register-prefetched W tiles (R6 shape: 128 thr, 24 f32x2 acc).
// ---------------------------------------------------------------------------
__global__ __launch_bounds__(128, 2)
void edge_kernel(const int* __restrict__ residue_idx,
                 const float* __restrict__ W_pos, const float* __restrict__ b_pos,
                 const float* __restrict__ W_e,
                 const float* __restrict__ ln_g, const float* __restrict__ ln_b,
                 float* __restrict__ outE) {
    extern __shared__ float sm[];
    float* featT = sm;                       // [416][48]
    float* Wsh   = sm + NIN * KNB;           // [32][128] row-major
    float* xj    = Wsh + 32 * 128;           // [48][15]
    float* xi    = xj + KNB * 15;            // [15] (+1 pad)
    int*   jn    = (int*)(xi + 16);          // [48]
    int*   offp  = jn + KNB;                 // [48]

    int row = blockIdx.x;
    int b = row / LL;
    int tid = threadIdx.x;

    // prefetch W tile 0 immediately (overlaps gather + feature phase)
    float4 pre[8];
    {
        const float4* src = (const float4*)W_e;
#pragma unroll
        for (int q = 0; q < 8; q++) pre[q] = src[tid + q * 128];
    }

    if (tid < 15) xi[tid] = g_Xall[row * 15 + tid];
    if (tid < KNB) {
        int j = g_Eidx[row * KNB + tid];
        jn[tid] = j;
        int d = residue_idx[row] - residue_idx[b * LL + j] + 32;
        d = min(max(d, 0), 64);
        offp[tid] = d;
    }
    __syncthreads();

    for (int t = tid; t < KNB * 15; t += 128) {
        int e = t / 15, cmp = t % 15;
        xj[t] = g_Xall[(b * LL + jn[e]) * 15 + cmp];
    }
    // positional features: feat[0..15]
    for (int t = tid; t < KNB * 16; t += 128) {
        int e = t % KNB, c = t / KNB;
        featT[c * KNB + e] = W_pos[offp[e] * 16 + c] + b_pos[c];
    }
    __syncthreads();

    // RBF features: feat[16 + (a*5+c)*16 + m]
    const float inv_sig = 1.0f / 1.25f;
    for (int t = tid; t < KNB * 25; t += 128) {
        int e = t % KNB, p = t / KNB;
        int a = p / 5, c = p % 5;
        float dx = xi[a * 3 + 0] - xj[e * 15 + c * 3 + 0];
        float dy = xi[a * 3 + 1] - xj[e * 15 + c * 3 + 1];
        float dz = xi[a * 3 + 2] - xj[e * 15 + c * 3 + 2];
        float d = sqrtf(dx * dx + dy * dy + dz * dz + 1e-6f);
        float* dst = featT + (16 + p * 16) * KNB + e;
#pragma unroll
        for (int m = 0; m < 16; m++) {
            float mu = 2.0f + (float)m * (20.0f / 15.0f);
            float z = (d - mu) * inv_sig;
            dst[m * KNB] = __expf(-z * z);
        }
    }

    int tx = tid >> 3, te = tid & 7;
    ull acc[24];
#pragma unroll
    for (int q = 0; q < 24; q++) acc[q] = 0ull;

    const ull* Wu = (const ull*)Wsh;

    for (int f0 = 0; f0 < NIN; f0 += 32) {
        __syncthreads();   // prev tile consumed; orders featT writes on iter 0
        {
            float4* dst4 = (float4*)Wsh;
#pragma unroll
            for (int q = 0; q < 8; q++) dst4[tid + q * 128] = pre[q];
        }
        __syncthreads();
        if (f0 + 32 < NIN) {
            const float4* src = (const float4*)(W_e + (f0 + 32) * 128);
#pragma unroll
            for (int q = 0; q < 8; q++) pre[q] = src[tid + q * 128];
        }
#pragma unroll 8
        for (int ff = 0; ff < 32; ff++) {
            ull w0 = Wu[ff * 64 + tx];
            ull w1 = Wu[ff * 64 + tx + 16];
            ull w2 = Wu[ff * 64 + tx + 32];
            ull w3 = Wu[ff * 64 + tx + 48];
            const ull* fu = (const ull*)(featT + (f0 + ff) * KNB) + te * 3;
            float2 f01 = unpack2(fu[0]);
            float2 f23 = unpack2(fu[1]);
            float2 f45 = unpack2(fu[2]);
            ull p0 = pack2(f01.x), p1 = pack2(f01.y);
            ull p2 = pack2(f23.x), p3 = pack2(f23.y);
            ull p4 = pack2(f45.x), p5 = pack2(f45.y);
            acc[0]  = fma2(w0, p0, acc[0]);
            acc[1]  = fma2(w1, p0, acc[1]);
            acc[2]  = fma2(w2, p0, acc[2]);
            acc[3]  = fma2(w3, p0, acc[3]);
            acc[4]  = fma2(w0, p1, acc[4]);
            acc[5]  = fma2(w1, p1, acc[5]);
            acc[6]  = fma2(w2, p1, acc[6]);
            acc[7]  = fma2(w3, p1, acc[7]);
            acc[8]  = fma2(w0, p2, acc[8]);
            acc[9]  = fma2(w1, p2, acc[9]);
            acc[10] = fma2(w2, p2, acc[10]);
            acc[11] = fma2(w3, p2, acc[11]);
            acc[12] = fma2(w0, p3, acc[12]);
            acc[13] = fma2(w1, p3, acc[13]);
            acc[14] = fma2(w2, p3, acc[14]);
            acc[15] = fma2(w3, p3, acc[15]);
            acc[16] = fma2(w0, p4, acc[16]);
            acc[17] = fma2(w1, p4, acc[17]);
            acc[18] = fma2(w2, p4, acc[18]);
            acc[19] = fma2(w3, p4, acc[19]);
            acc[20] = fma2(w0, p5, acc[20]);
            acc[21] = fma2(w1, p5, acc[21]);
            acc[22] = fma2(w2, p5, acc[22]);
            acc[23] = fma2(w3, p5, acc[23]);
        }
    }
    __syncthreads();       // GEMM reads of featT done; reuse it as E staging

    float* Esh = featT;    // [48][EPITCH]
#pragma unroll
    for (int e = 0; e < 6; e++) {
        int edge = te * 6 + e;
#pragma unroll
        for (int p = 0; p < 4; p++) {
            float2 c = unpack2(acc[e * 4 + p]);
            *(float2*)(Esh + edge * EPITCH + (tx + 16 * p) * 2) = c;
        }
    }
    __syncthreads();

    // LayerNorm: warp w handles edges w*12 .. w*12+11
    int w = tid >> 5, lane = tid & 31;
    for (int e = w * 12; e < w * 12 + 12; e++) {
        float v0 = Esh[e * EPITCH + lane];
        float v1 = Esh[e * EPITCH + lane + 32];
        float v2 = Esh[e * EPITCH + lane + 64];
        float v3 = Esh[e * EPITCH + lane + 96];
        float s  = v0 + v1 + v2 + v3;
        float ss = v0 * v0 + v1 * v1 + v2 * v2 + v3 * v3;
#pragma unroll
        for (int o = 16; o > 0; o >>= 1) {
            s  += __shfl_xor_sync(0xffffffffu, s, o);
            ss += __shfl_xor_sync(0xffffffffu, ss, o);
        }
        float mean = s * (1.0f / 128.0f);
        float var  = ss * (1.0f / 128.0f) - mean * mean;
        float rstd = rsqrtf(var + 1e-5f);
        size_t base = ((size_t)row * KNB + e) * 128;
        outE[base + lane]      = (v0 - mean) * rstd * ln_g[lane]      + ln_b[lane];
        outE[base + lane + 32] = (v1 - mean) * rstd * ln_g[lane + 32] + ln_b[lane + 32];
        outE[base + lane + 64] = (v2 - mean) * rstd * ln_g[lane + 64] + ln_b[lane + 64];
        outE[base + lane + 96] = (v3 - mean) * rstd * ln_g[lane + 96] + ln_b[lane + 96];
    }
}

// ---------------------------------------------------------------------------
extern "C" void kernel_launch(void* const* d_in, const int* in_sizes, int n_in,
                              void* d_out, int out_size) {
    const float* X     = (const float*)d_in[0];
    const int*   S     = (const int*)d_in[2];
    const int*   ridx  = (const int*)d_in[3];
    const int*   table = (const int*)d_in[5];
    const float* W_pos = (const float*)d_in[6];
    const float* b_pos = (const float*)d_in[7];
    const float* W_e   = (const float*)d_in[8];
    const float* ln_g  = (const float*)d_in[9];
    const float* ln_b  = (const float*)d_in[10];
    float* out = (float*)d_out;

    const size_t E_elems = (size_t)NRES * KNB * NOUT;       // 25,165,824
    int write_idx = (out_size >= (int)(E_elems + (size_t)NRES * KNB)) ? 1 : 0;

    build_xall_kernel<<<(NRES + 255) / 256, 256>>>(X, S, table);
    topk_kernel<<<NRES, 256>>>(out + E_elems, write_idx);

    size_t smem = (size_t)(NIN * KNB + 32 * 128 + KNB * 15 + 16) * sizeof(float)
                + (size_t)(2 * KNB) * sizeof(int);
    cudaFuncSetAttribute(edge_kernel, cudaFuncAttributeMaxDynamicSharedMemorySize, (int)smem);
    edge_kernel<<<NRES, 128, smem>>>(ridx, W_pos, b_pos, W_e, ln_g, ln_b, out);
}

// round 11
// speedup vs baseline: 2.3407x; 1.6463x over previous
#include <cuda_runtime.h>
#include <cuda_bf16.h>
#include <math.h>

#define BB   2
#define LL   2048
#define NRES 4096
#define KNB  48
#define NIN  416
#define NOUT 128
#define EPITCH 132
#define NKS  26              // 416 / 16
#define FPITCH 848           // featT row pitch bytes (16*53, ldmatrix conflict-free)

// smem byte offsets
#define SMB_FH  0                            // feat hi: 48 * 848 = 40704
#define SMB_FL  40704                        // feat lo: 40704
#define SMB_XJ  81408                        // 48*15 floats = 2880
#define SMB_XI  84288                        // 16 floats
#define SMB_JN  84352                        // 48 int
#define SMB_OFF 84544                        // 48 int
#define SMB_TOT 84800

typedef unsigned long long ull;

// device scratch (no allocations allowed)
__device__ float g_Xall[NRES * 15];
__device__ int   g_Eidx[NRES * KNB];
// W in mma B-fragment order: idx = (ks*16 + nt)*32 + lane, uint2 = {b0, b1}
__device__ uint2 g_WfHi[NKS * 16 * 32];
__device__ uint2 g_WfLo[NKS * 16 * 32];

__device__ __forceinline__ unsigned smem_u32(const void* p) {
    unsigned a;
    asm("{ .reg .u64 t; cvta.to.shared.u64 t, %1; cvt.u32.u64 %0, t; }"
        : "=r"(a) : "l"(p));
    return a;
}
__device__ __forceinline__ void ldm4(unsigned* r, unsigned addr) {
    asm volatile("ldmatrix.sync.aligned.m8n8.x4.shared.b16 {%0,%1,%2,%3}, [%4];"
        : "=r"(r[0]), "=r"(r[1]), "=r"(r[2]), "=r"(r[3]) : "r"(addr));
}
__device__ __forceinline__ void mma16816(float* d, const unsigned* a, uint2 b) {
    asm volatile("mma.sync.aligned.m16n8k16.row.col.f32.bf16.bf16.f32 "
        "{%0,%1,%2,%3}, {%4,%5,%6,%7}, {%8,%9}, {%0,%1,%2,%3};"
        : "+f"(d[0]), "+f"(d[1]), "+f"(d[2]), "+f"(d[3])
        : "r"(a[0]), "r"(a[1]), "r"(a[2]), "r"(a[3]), "r"(b.x), "r"(b.y));
}
__device__ __forceinline__ unsigned pack_bf16(float v0, float v1) {
    __nv_bfloat16 h0 = __float2bfloat16(v0), h1 = __float2bfloat16(v1);
    return ((unsigned)__bfloat16_as_ushort(h1) << 16) | __bfloat16_as_ushort(h0);
}
__device__ __forceinline__ void split_store(char* bh, char* bl, unsigned off,
                                            float v0, float v1) {
    __nv_bfloat16 h0 = __float2bfloat16(v0), h1 = __float2bfloat16(v1);
    float r0 = v0 - __bfloat162float(h0), r1 = v1 - __bfloat162float(h1);
    *(unsigned*)(bh + off) = ((unsigned)__bfloat16_as_ushort(h1) << 16) | __bfloat16_as_ushort(h0);
    *(unsigned*)(bl + off) = pack_bf16(r0, r1);
}

// ---------------------------------------------------------------------------
// Kernel 0: W -> bf16 hi/lo in mma B-fragment order
// ---------------------------------------------------------------------------
__global__ void prep_w_kernel(const float* __restrict__ W_e) {
    int idx = blockIdx.x * 256 + threadIdx.x;       // 416*32 = 13312 items
    if (idx >= NKS * 16 * 32) return;
    int l = idx & 31, t = idx >> 5;
    int ks = t >> 4, nt = t & 15;
    int g = l >> 2, tg = l & 3;
    int k0 = ks * 16 + 2 * tg, n = nt * 8 + g;
    float v00 = W_e[k0 * 128 + n],       v01 = W_e[(k0 + 1) * 128 + n];
    float v10 = W_e[(k0 + 8) * 128 + n], v11 = W_e[(k0 + 9) * 128 + n];
    __nv_bfloat16 h00 = __float2bfloat16(v00), h01 = __float2bfloat16(v01);
    __nv_bfloat16 h10 = __float2bfloat16(v10), h11 = __float2bfloat16(v11);
    g_WfHi[idx] = make_uint2(
        ((unsigned)__bfloat16_as_ushort(h01) << 16) | __bfloat16_as_ushort(h00),
        ((unsigned)__bfloat16_as_ushort(h11) << 16) | __bfloat16_as_ushort(h10));
    g_WfLo[idx] = make_uint2(
        pack_bf16(v00 - __bfloat162float(h00), v01 - __bfloat162float(h01)),
        pack_bf16(v10 - __bfloat162float(h10), v11 - __bfloat162float(h11)));
}

// ---------------------------------------------------------------------------
// Kernel 1: gather backbone atoms, build virtual atom
// ---------------------------------------------------------------------------
__global__ void build_xall_kernel(const float* __restrict__ X,
                                  const int* __restrict__ S,
                                  const int* __restrict__ table) {
    int g = blockIdx.x * blockDim.x + threadIdx.x;
    if (g >= NRES) return;
    int s = S[g];
    const float* Xr = X + (size_t)g * 14 * 3;
    float bb[12];
#pragma unroll
    for (int a = 0; a < 4; a++) {
        int ai = table[s * 4 + a];
        bb[a * 3 + 0] = Xr[ai * 3 + 0];
        bb[a * 3 + 1] = Xr[ai * 3 + 1];
        bb[a * 3 + 2] = Xr[ai * 3 + 2];
    }
    float b1x = bb[0] - bb[3], b1y = bb[1] - bb[4], b1z = bb[2] - bb[5];
    float b2x = bb[6] - bb[3], b2y = bb[7] - bb[4], b2z = bb[8] - bb[5];
    float nx = b1y * b2z - b1z * b2y;
    float ny = b1z * b2x - b1x * b2z;
    float nz = b1x * b2y - b1y * b2x;
    const float wN = 0.58273431f, w1 = -0.56802827f, w2 = -0.54067466f;
    float vx = wN * nx + w1 * b1x + w2 * b2x + bb[3];
    float vy = wN * ny + w1 * b1y + w2 * b2y + bb[4];
    float vz = wN * nz + w1 * b1z + w2 * b2z + bb[5];
    float* o = g_Xall + g * 15;
#pragma unroll
    for (int t = 0; t < 12; t++) o[t] = bb[t];
    o[12] = vx; o[13] = vy; o[14] = vz;
}

// ---------------------------------------------------------------------------
// Kernel 2: top-48 by 2-level radix select (proven, unchanged)
// ---------------------------------------------------------------------------
__global__ void topk_kernel(float* __restrict__ outEidxF, int write_idx_out) {
    __shared__ unsigned ud[LL];
    __shared__ int      hist[256];
    __shared__ unsigned cand_u[LL];
    __shared__ int      cand_i[LL];
    __shared__ unsigned sel_u[KNB];
    __shared__ int      sel_i[KNB];
    __shared__ int s_E, s_cA, s_M, s_c0, s_nsel, s_ncand;

    int row = blockIdx.x;
    int b = row / LL;
    int tid = threadIdx.x;

    const float* ca_i = g_Xall + row * 15 + 3;
    float cx = ca_i[0], cy = ca_i[1], cz = ca_i[2];
    for (int j = tid; j < LL; j += 256) {
        const float* cj = g_Xall + (b * LL + j) * 15 + 3;
        float dx = cx - cj[0], dy = cy - cj[1], dz = cz - cj[2];
        float d = sqrtf(dx * dx + dy * dy + dz * dz + 1e-6f);
        ud[j] = __float_as_uint(d);
    }
    hist[tid] = 0;
    if (tid == 0) { s_nsel = 0; s_ncand = 0; }
    __syncthreads();

    for (int j = tid; j < LL; j += 256) atomicAdd(&hist[ud[j] >> 23], 1);
    __syncthreads();
    if (tid < 32) {
        int base = tid * 8, loc[8], s = 0;
#pragma unroll
        for (int k = 0; k < 8; k++) { loc[k] = hist[base + k]; s += loc[k]; }
        int pre = s;
#pragma unroll
        for (int o = 1; o < 32; o <<= 1) {
            int v = __shfl_up_sync(0xffffffffu, pre, o);
            if (tid >= o) pre += v;
        }
        int excl = pre - s;
        if (excl < KNB && pre >= KNB) {
            int c = excl;
#pragma unroll
            for (int k = 0; k < 8; k++) {
                if (c + loc[k] >= KNB) { s_E = base + k; s_cA = c; break; }
                c += loc[k];
            }
        }
    }
    __syncthreads();
    int E = s_E, cA = s_cA, target2 = KNB - cA;
    hist[tid] = 0;
    __syncthreads();

    for (int j = tid; j < LL; j += 256) {
        unsigned u = ud[j];
        if ((int)(u >> 23) == E) atomicAdd(&hist[(u >> 15) & 0xFF], 1);
    }
    __syncthreads();
    if (tid < 32) {
        int base = tid * 8, loc[8], s = 0;
#pragma unroll
        for (int k = 0; k < 8; k++) { loc[k] = hist[base + k]; s += loc[k]; }
        int pre = s;
#pragma unroll
        for (int o = 1; o < 32; o <<= 1) {
            int v = __shfl_up_sync(0xffffffffu, pre, o);
            if (tid >= o) pre += v;
        }
        int excl = pre - s;
        if (excl < target2 && pre >= target2) {
            int c = excl;
#pragma unroll
            for (int k = 0; k < 8; k++) {
                if (c + loc[k] >= target2) { s_M = base + k; s_c0 = cA + c; break; }
                c += loc[k];
            }
        }
    }
    __syncthreads();
    unsigned T17 = ((unsigned)E << 8) | (unsigned)s_M;
    int c0 = s_c0;

    for (int j = tid; j < LL; j += 256) {
        unsigned u = ud[j], k17 = u >> 15;
        if (k17 < T17) {
            int p = atomicAdd(&s_nsel, 1);
            sel_u[p] = u; sel_i[p] = j;
        } else if (k17 == T17) {
            int p = atomicAdd(&s_ncand, 1);
            cand_u[p] = u; cand_i[p] = j;
        }
    }
    __syncthreads();

    int need = KNB - c0;
    int s = s_ncand;
    for (int c = tid; c < s; c += 256) {
        unsigned u = cand_u[c]; int i = cand_i[c]; int r = 0;
        for (int c2 = 0; c2 < s; c2++) {
            unsigned u2 = cand_u[c2]; int i2 = cand_i[c2];
            if (u2 < u || (u2 == u && i2 < i)) r++;
        }
        if (r < need) { sel_u[c0 + r] = u; sel_i[c0 + r] = i; }
    }
    __syncthreads();

    for (int t = tid; t < KNB; t += 256) {
        if (t < c0) {
            unsigned u = sel_u[t]; int i = sel_i[t]; int r = 0;
            for (int t2 = 0; t2 < c0; t2++) {
                unsigned u2 = sel_u[t2]; int i2 = sel_i[t2];
                if (u2 < u || (u2 == u && i2 < i)) r++;
            }
            g_Eidx[row * KNB + r] = i;
            if (write_idx_out) outEidxF[(size_t)row * KNB + r] = (float)i;
        } else {
            int i = sel_i[t];
            g_Eidx[row * KNB + t] = i;
            if (write_idx_out) outEidxF[(size_t)row * KNB + t] = (float)i;
        }
    }
}

// ---------------------------------------------------------------------------
// Kernel 3: features (bf16 hi/lo) + mma.sync bf16 3-term GEMM + LN.
// One block per residue; warp w owns n-tiles 4w..4w+3 (32 channels).
// ---------------------------------------------------------------------------
__global__ __launch_bounds__(128)
void edge_kernel(const int* __restrict__ residue_idx,
                 const float* __restrict__ W_pos, const float* __restrict__ b_pos,
                 const float* __restrict__ ln_g, const float* __restrict__ ln_b,
                 float* __restrict__ outE) {
    extern __shared__ char smc[];
    float* smf = (float*)smc;
    unsigned smem_base = smem_u32(smc);

    int row = blockIdx.x;
    int b = row / LL;
    int tid = threadIdx.x;
    int wid = tid >> 5, lane = tid & 31;

    char* fh = smc + SMB_FH;
    char* fl = smc + SMB_FL;
    float* xj = (float*)(smc + SMB_XJ);
    float* xi = (float*)(smc + SMB_XI);
    int*   jn = (int*)(smc + SMB_JN);
    int*   offp = (int*)(smc + SMB_OFF);

    if (tid < 15) xi[tid] = g_Xall[row * 15 + tid];
    if (tid < KNB) {
        int j = g_Eidx[row * KNB + tid];
        jn[tid] = j;
        int d = residue_idx[row] - residue_idx[b * LL + j] + 32;
        d = min(max(d, 0), 64);
        offp[tid] = d;
    }
    __syncthreads();
    for (int t = tid; t < KNB * 15; t += 128) {
        int e = t / 15, cmp = t % 15;
        xj[t] = g_Xall[(b * LL + jn[e]) * 15 + cmp];
    }
    __syncthreads();

    // fill featT (bf16 hi/lo), row = edge (pitch 848B), col = feature
    const float inv_sig = 1.0f / 1.25f;
    for (int t = tid; t < KNB * 26; t += 128) {
        int e = t % KNB, g = t / KNB;
        char* rh = fh + e * FPITCH;
        char* rl = fl + e * FPITCH;
        if (g == 0) {
            const float* wp = W_pos + offp[e] * 16;
#pragma unroll
            for (int k2 = 0; k2 < 8; k2++) {
                float v0 = wp[2 * k2] + b_pos[2 * k2];
                float v1 = wp[2 * k2 + 1] + b_pos[2 * k2 + 1];
                split_store(rh, rl, 4 * k2, v0, v1);
            }
        } else {
            int p = g - 1, a = p / 5, cc = p % 5;
            float dx = xi[a * 3 + 0] - xj[e * 15 + cc * 3 + 0];
            float dy = xi[a * 3 + 1] - xj[e * 15 + cc * 3 + 1];
            float dz = xi[a * 3 + 2] - xj[e * 15 + cc * 3 + 2];
            float d = sqrtf(dx * dx + dy * dy + dz * dz + 1e-6f);
            unsigned kb = (unsigned)(16 + p * 16) * 2;
#pragma unroll
            for (int m2 = 0; m2 < 8; m2++) {
                float mu0 = 2.0f + (float)(2 * m2) * (20.0f / 15.0f);
                float mu1 = 2.0f + (float)(2 * m2 + 1) * (20.0f / 15.0f);
                float z0 = (d - mu0) * inv_sig, z1 = (d - mu1) * inv_sig;
                split_store(rh, rl, kb + 4 * m2, __expf(-z0 * z0), __expf(-z1 * z1));
            }
        }
    }
    __syncthreads();

    // ---- mma mainloop ----
    // ldmatrix lane address: row = m*16 + ((lane>>3)&1)*8 + (lane&7),
    //                        col byte = ks*32 + (lane>>4)*16
    int lrow = ((lane >> 3) & 1) * 8 + (lane & 7);
    unsigned aoff = (unsigned)lrow * FPITCH + ((unsigned)(lane >> 4)) * 16;
    unsigned ah_base = smem_base + SMB_FH + aoff;
    unsigned al_base = smem_base + SMB_FL + aoff;

    float acc[3][4][4];
#pragma unroll
    for (int m = 0; m < 3; m++)
#pragma unroll
        for (int j = 0; j < 4; j++)
#pragma unroll
            for (int q = 0; q < 4; q++) acc[m][j][q] = 0.0f;

    const uint2* bH = g_WfHi + (wid * 4) * 32 + lane;
    const uint2* bL = g_WfLo + (wid * 4) * 32 + lane;
    uint2 Bh[4], Bl[4], Bh2[4], Bl2[4];
#pragma unroll
    for (int j = 0; j < 4; j++) { Bh[j] = bH[j * 32]; Bl[j] = bL[j * 32]; }

    for (int ks = 0; ks < NKS; ks++) {
        if (ks < NKS - 1) {
#pragma unroll
            for (int j = 0; j < 4; j++) {
                Bh2[j] = bH[(ks + 1) * 512 + j * 32];
                Bl2[j] = bL[(ks + 1) * 512 + j * 32];
            }
        }
        unsigned Ah[3][4], Al[3][4];
#pragma unroll
        for (int m = 0; m < 3; m++) ldm4(Ah[m], ah_base + m * (16 * FPITCH) + ks * 32);
#pragma unroll
        for (int m = 0; m < 3; m++) ldm4(Al[m], al_base + m * (16 * FPITCH) + ks * 32);
#pragma unroll
        for (int m = 0; m < 3; m++) {
#pragma unroll
            for (int j = 0; j < 4; j++) {
                mma16816(acc[m][j], Ah[m], Bh[j]);
                mma16816(acc[m][j], Ah[m], Bl[j]);
                mma16816(acc[m][j], Al[m], Bh[j]);
            }
        }
#pragma unroll
        for (int j = 0; j < 4; j++) { Bh[j] = Bh2[j]; Bl[j] = Bl2[j]; }
    }
    __syncthreads();   // featT dead; reuse as Esh

    // write D frags to Esh[edge][ch]
    float* Esh = smf;  // [48][EPITCH] = 25.3 KB, aliases featT
    int g = lane >> 2, tg = lane & 3;
#pragma unroll
    for (int m = 0; m < 3; m++) {
#pragma unroll
        for (int j = 0; j < 4; j++) {
            int ch = (wid * 4 + j) * 8 + 2 * tg;
            int e0 = m * 16 + g;
            Esh[e0 * EPITCH + ch]            = acc[m][j][0];
            Esh[e0 * EPITCH + ch + 1]        = acc[m][j][1];
            Esh[(e0 + 8) * EPITCH + ch]      = acc[m][j][2];
            Esh[(e0 + 8) * EPITCH + ch + 1]  = acc[m][j][3];
        }
    }
    __syncthreads();

    // LayerNorm: warp w handles edges w*12 .. w*12+11
    for (int e = wid * 12; e < wid * 12 + 12; e++) {
        float v0 = Esh[e * EPITCH + lane];
        float v1 = Esh[e * EPITCH + lane + 32];
        float v2 = Esh[e * EPITCH + lane + 64];
        float v3 = Esh[e * EPITCH + lane + 96];
        float s  = v0 + v1 + v2 + v3;
        float ss = v0 * v0 + v1 * v1 + v2 * v2 + v3 * v3;
#pragma unroll
        for (int o = 16; o > 0; o >>= 1) {
            s  += __shfl_xor_sync(0xffffffffu, s, o);
            ss += __shfl_xor_sync(0xffffffffu, ss, o);
        }
        float mean = s * (1.0f / 128.0f);
        float var  = ss * (1.0f / 128.0f) - mean * mean;
        float rstd = rsqrtf(var + 1e-5f);
        size_t base = ((size_t)row * KNB + e) * 128;
        outE[base + lane]      = (v0 - mean) * rstd * ln_g[lane]      + ln_b[lane];
        outE[base + lane + 32] = (v1 - mean) * rstd * ln_g[lane + 32] + ln_b[lane + 32];
        outE[base + lane + 64] = (v2 - mean) * rstd * ln_g[lane + 64] + ln_b[lane + 64];
        outE[base + lane + 96] = (v3 - mean) * rstd * ln_g[lane + 96] + ln_b[lane + 96];
    }
}

// ---------------------------------------------------------------------------
extern "C" void kernel_launch(void* const* d_in, const int* in_sizes, int n_in,
                              void* d_out, int out_size) {
    const float* X     = (const float*)d_in[0];
    const int*   S     = (const int*)d_in[2];
    const int*   ridx  = (const int*)d_in[3];
    const int*   table = (const int*)d_in[5];
    const float* W_pos = (const float*)d_in[6];
    const float* b_pos = (const float*)d_in[7];
    const float* W_e   = (const float*)d_in[8];
    const float* ln_g  = (const float*)d_in[9];
    const float* ln_b  = (const float*)d_in[10];
    float* out = (float*)d_out;

    const size_t E_elems = (size_t)NRES * KNB * NOUT;
    int write_idx = (out_size >= (int)(E_elems + (size_t)NRES * KNB)) ? 1 : 0;

    build_xall_kernel<<<(NRES + 255) / 256, 256>>>(X, S, table);
    prep_w_kernel<<<(NKS * 16 * 32 + 255) / 256, 256>>>(W_e);
    topk_kernel<<<NRES, 256>>>(out + E_elems, write_idx);

    cudaFuncSetAttribute(edge_kernel, cudaFuncAttributeMaxDynamicSharedMemorySize, SMB_TOT);
    edge_kernel<<<NRES, 128, SMB_TOT>>>(ridx, W_pos, b_pos, ln_g, ln_b, out);
}

// round 12
// speedup vs baseline: 2.7214x; 1.1626x over previous
#include <cuda_runtime.h>
#include <cuda_bf16.h>
#include <math.h>

#define BB   2
#define LL   2048
#define NRES 4096
#define KNB  48
#define NIN  416
#define NOUT 128
#define EPITCH 132
#define NKS  26              // 416 / 16
#define FPITCH 848           // featT row pitch bytes (16*53, ldmatrix conflict-free)

// smem byte offsets
#define SMB_FH  0                            // feat hi: 48 * 848 = 40704
#define SMB_FL  40704                        // feat lo: 40704
#define SMB_XJ  81408                        // 48*15 floats = 2880
#define SMB_XI  84288                        // 16 floats
#define SMB_JN  84352                        // 48 int
#define SMB_OFF 84544                        // 48 int
#define SMB_TOT 84800

typedef unsigned long long ull;

// device scratch (no allocations allowed)
__device__ float g_Xall[NRES * 15];
__device__ int   g_Eidx[NRES * KNB];
// W in mma B-fragment order: idx = (ks*16 + nt)*32 + lane, uint2 = {b0, b1}
__device__ uint2 g_WfHi[NKS * 16 * 32];
__device__ uint2 g_WfLo[NKS * 16 * 32];

__device__ __forceinline__ unsigned smem_u32(const void* p) {
    unsigned a;
    asm("{ .reg .u64 t; cvta.to.shared.u64 t, %1; cvt.u32.u64 %0, t; }"
        : "=r"(a) : "l"(p));
    return a;
}
__device__ __forceinline__ void ldm4(unsigned* r, unsigned addr) {
    asm volatile("ldmatrix.sync.aligned.m8n8.x4.shared.b16 {%0,%1,%2,%3}, [%4];"
        : "=r"(r[0]), "=r"(r[1]), "=r"(r[2]), "=r"(r[3]) : "r"(addr));
}
__device__ __forceinline__ void mma16816(float* d, const unsigned* a, uint2 b) {
    asm volatile("mma.sync.aligned.m16n8k16.row.col.f32.bf16.bf16.f32 "
        "{%0,%1,%2,%3}, {%4,%5,%6,%7}, {%8,%9}, {%0,%1,%2,%3};"
        : "+f"(d[0]), "+f"(d[1]), "+f"(d[2]), "+f"(d[3])
        : "r"(a[0]), "r"(a[1]), "r"(a[2]), "r"(a[3]), "r"(b.x), "r"(b.y));
}
__device__ __forceinline__ unsigned pack_bf16(float v0, float v1) {
    __nv_bfloat16 h0 = __float2bfloat16(v0), h1 = __float2bfloat16(v1);
    return ((unsigned)__bfloat16_as_ushort(h1) << 16) | __bfloat16_as_ushort(h0);
}
__device__ __forceinline__ void split_store(char* bh, char* bl, unsigned off,
                                            float v0, float v1) {
    __nv_bfloat16 h0 = __float2bfloat16(v0), h1 = __float2bfloat16(v1);
    float r0 = v0 - __bfloat162float(h0), r1 = v1 - __bfloat162float(h1);
    *(unsigned*)(bh + off) = ((unsigned)__bfloat16_as_ushort(h1) << 16) | __bfloat16_as_ushort(h0);
    *(unsigned*)(bl + off) = pack_bf16(r0, r1);
}

// ---------------------------------------------------------------------------
// Kernel 0: W -> bf16 hi/lo in mma B-fragment order
// ---------------------------------------------------------------------------
__global__ void prep_w_kernel(const float* __restrict__ W_e) {
    int idx = blockIdx.x * 256 + threadIdx.x;       // 416*32 = 13312 items
    if (idx >= NKS * 16 * 32) return;
    int l = idx & 31, t = idx >> 5;
    int ks = t >> 4, nt = t & 15;
    int g = l >> 2, tg = l & 3;
    int k0 = ks * 16 + 2 * tg, n = nt * 8 + g;
    float v00 = W_e[k0 * 128 + n],       v01 = W_e[(k0 + 1) * 128 + n];
    float v10 = W_e[(k0 + 8) * 128 + n], v11 = W_e[(k0 + 9) * 128 + n];
    __nv_bfloat16 h00 = __float2bfloat16(v00), h01 = __float2bfloat16(v01);
    __nv_bfloat16 h10 = __float2bfloat16(v10), h11 = __float2bfloat16(v11);
    g_WfHi[idx] = make_uint2(
        ((unsigned)__bfloat16_as_ushort(h01) << 16) | __bfloat16_as_ushort(h00),
        ((unsigned)__bfloat16_as_ushort(h11) << 16) | __bfloat16_as_ushort(h10));
    g_WfLo[idx] = make_uint2(
        pack_bf16(v00 - __bfloat162float(h00), v01 - __bfloat162float(h01)),
        pack_bf16(v10 - __bfloat162float(h10), v11 - __bfloat162float(h11)));
}

// ---------------------------------------------------------------------------
// Kernel 1: gather backbone atoms, build virtual atom
// ---------------------------------------------------------------------------
__global__ void build_xall_kernel(const float* __restrict__ X,
                                  const int* __restrict__ S,
                                  const int* __restrict__ table) {
    int g = blockIdx.x * blockDim.x + threadIdx.x;
    if (g >= NRES) return;
    int s = S[g];
    const float* Xr = X + (size_t)g * 14 * 3;
    float bb[12];
#pragma unroll
    for (int a = 0; a < 4; a++) {
        int ai = table[s * 4 + a];
        bb[a * 3 + 0] = Xr[ai * 3 + 0];
        bb[a * 3 + 1] = Xr[ai * 3 + 1];
        bb[a * 3 + 2] = Xr[ai * 3 + 2];
    }
    float b1x = bb[0] - bb[3], b1y = bb[1] - bb[4], b1z = bb[2] - bb[5];
    float b2x = bb[6] - bb[3], b2y = bb[7] - bb[4], b2z = bb[8] - bb[5];
    float nx = b1y * b2z - b1z * b2y;
    float ny = b1z * b2x - b1x * b2z;
    float nz = b1x * b2y - b1y * b2x;
    const float wN = 0.58273431f, w1 = -0.56802827f, w2 = -0.54067466f;
    float vx = wN * nx + w1 * b1x + w2 * b2x + bb[3];
    float vy = wN * ny + w1 * b1y + w2 * b2y + bb[4];
    float vz = wN * nz + w1 * b1z + w2 * b2z + bb[5];
    float* o = g_Xall + g * 15;
#pragma unroll
    for (int t = 0; t < 12; t++) o[t] = bb[t];
    o[12] = vx; o[13] = vy; o[14] = vz;
}

// ---------------------------------------------------------------------------
// Kernel 2: top-48 by 2-level radix select (proven, unchanged)
// ---------------------------------------------------------------------------
__global__ void topk_kernel(float* __restrict__ outEidxF, int write_idx_out) {
    __shared__ unsigned ud[LL];
    __shared__ int      hist[256];
    __shared__ unsigned cand_u[LL];
    __shared__ int      cand_i[LL];
    __shared__ unsigned sel_u[KNB];
    __shared__ int      sel_i[KNB];
    __shared__ int s_E, s_cA, s_M, s_c0, s_nsel, s_ncand;

    int row = blockIdx.x;
    int b = row / LL;
    int tid = threadIdx.x;

    const float* ca_i = g_Xall + row * 15 + 3;
    float cx = ca_i[0], cy = ca_i[1], cz = ca_i[2];
    for (int j = tid; j < LL; j += 256) {
        const float* cj = g_Xall + (b * LL + j) * 15 + 3;
        float dx = cx - cj[0], dy = cy - cj[1], dz = cz - cj[2];
        float d = sqrtf(dx * dx + dy * dy + dz * dz + 1e-6f);
        ud[j] = __float_as_uint(d);
    }
    hist[tid] = 0;
    if (tid == 0) { s_nsel = 0; s_ncand = 0; }
    __syncthreads();

    for (int j = tid; j < LL; j += 256) atomicAdd(&hist[ud[j] >> 23], 1);
    __syncthreads();
    if (tid < 32) {
        int base = tid * 8, loc[8], s = 0;
#pragma unroll
        for (int k = 0; k < 8; k++) { loc[k] = hist[base + k]; s += loc[k]; }
        int pre = s;
#pragma unroll
        for (int o = 1; o < 32; o <<= 1) {
            int v = __shfl_up_sync(0xffffffffu, pre, o);
            if (tid >= o) pre += v;
        }
        int excl = pre - s;
        if (excl < KNB && pre >= KNB) {
            int c = excl;
#pragma unroll
            for (int k = 0; k < 8; k++) {
                if (c + loc[k] >= KNB) { s_E = base + k; s_cA = c; break; }
                c += loc[k];
            }
        }
    }
    __syncthreads();
    int E = s_E, cA = s_cA, target2 = KNB - cA;
    hist[tid] = 0;
    __syncthreads();

    for (int j = tid; j < LL; j += 256) {
        unsigned u = ud[j];
        if ((int)(u >> 23) == E) atomicAdd(&hist[(u >> 15) & 0xFF], 1);
    }
    __syncthreads();
    if (tid < 32) {
        int base = tid * 8, loc[8], s = 0;
#pragma unroll
        for (int k = 0; k < 8; k++) { loc[k] = hist[base + k]; s += loc[k]; }
        int pre = s;
#pragma unroll
        for (int o = 1; o < 32; o <<= 1) {
            int v = __shfl_up_sync(0xffffffffu, pre, o);
            if (tid >= o) pre += v;
        }
        int excl = pre - s;
        if (excl < target2 && pre >= target2) {
            int c = excl;
#pragma unroll
            for (int k = 0; k < 8; k++) {
                if (c + loc[k] >= target2) { s_M = base + k; s_c0 = cA + c; break; }
                c += loc[k];
            }
        }
    }
    __syncthreads();
    unsigned T17 = ((unsigned)E << 8) | (unsigned)s_M;
    int c0 = s_c0;

    for (int j = tid; j < LL; j += 256) {
        unsigned u = ud[j], k17 = u >> 15;
        if (k17 < T17) {
            int p = atomicAdd(&s_nsel, 1);
            sel_u[p] = u; sel_i[p] = j;
        } else if (k17 == T17) {
            int p = atomicAdd(&s_ncand, 1);
            cand_u[p] = u; cand_i[p] = j;
        }
    }
    __syncthreads();

    int need = KNB - c0;
    int s = s_ncand;
    for (int c = tid; c < s; c += 256) {
        unsigned u = cand_u[c]; int i = cand_i[c]; int r = 0;
        for (int c2 = 0; c2 < s; c2++) {
            unsigned u2 = cand_u[c2]; int i2 = cand_i[c2];
            if (u2 < u || (u2 == u && i2 < i)) r++;
        }
        if (r < need) { sel_u[c0 + r] = u; sel_i[c0 + r] = i; }
    }
    __syncthreads();

    for (int t = tid; t < KNB; t += 256) {
        if (t < c0) {
            unsigned u = sel_u[t]; int i = sel_i[t]; int r = 0;
            for (int t2 = 0; t2 < c0; t2++) {
                unsigned u2 = sel_u[t2]; int i2 = sel_i[t2];
                if (u2 < u || (u2 == u && i2 < i)) r++;
            }
            g_Eidx[row * KNB + r] = i;
            if (write_idx_out) outEidxF[(size_t)row * KNB + r] = (float)i;
        } else {
            int i = sel_i[t];
            g_Eidx[row * KNB + t] = i;
            if (write_idx_out) outEidxF[(size_t)row * KNB + t] = (float)i;
        }
    }
}

// ---------------------------------------------------------------------------
// Kernel 3: features (bf16 hi/lo) + mma.sync bf16 3-term GEMM + LN.
// 256 threads; warp w owns n-tiles 2w..2w+1 (16 channels).
// ---------------------------------------------------------------------------
__global__ __launch_bounds__(256)
void edge_kernel(const int* __restrict__ residue_idx,
                 const float* __restrict__ W_pos, const float* __restrict__ b_pos,
                 const float* __restrict__ ln_g, const float* __restrict__ ln_b,
                 float* __restrict__ outE) {
    extern __shared__ char smc[];
    float* smf = (float*)smc;
    unsigned smem_base = smem_u32(smc);

    int row = blockIdx.x;
    int b = row / LL;
    int tid = threadIdx.x;
    int wid = tid >> 5, lane = tid & 31;

    char* fh = smc + SMB_FH;
    char* fl = smc + SMB_FL;
    float* xj = (float*)(smc + SMB_XJ);
    float* xi = (float*)(smc + SMB_XI);
    int*   jn = (int*)(smc + SMB_JN);
    int*   offp = (int*)(smc + SMB_OFF);

    if (tid < 15) xi[tid] = g_Xall[row * 15 + tid];
    if (tid < KNB) {
        int j = g_Eidx[row * KNB + tid];
        jn[tid] = j;
        int d = residue_idx[row] - residue_idx[b * LL + j] + 32;
        d = min(max(d, 0), 64);
        offp[tid] = d;
    }
    __syncthreads();
    for (int t = tid; t < KNB * 15; t += 256) {
        int e = t / 15, cmp = t % 15;
        xj[t] = g_Xall[(b * LL + jn[e]) * 15 + cmp];
    }
    __syncthreads();

    // fill featT (bf16 hi/lo), row = edge (pitch 848B), col = feature
    const float inv_sig = 1.0f / 1.25f;
    for (int t = tid; t < KNB * 26; t += 256) {
        int e = t % KNB, g = t / KNB;
        char* rh = fh + e * FPITCH;
        char* rl = fl + e * FPITCH;
        if (g == 0) {
            const float* wp = W_pos + offp[e] * 16;
#pragma unroll
            for (int k2 = 0; k2 < 8; k2++) {
                float v0 = wp[2 * k2] + b_pos[2 * k2];
                float v1 = wp[2 * k2 + 1] + b_pos[2 * k2 + 1];
                split_store(rh, rl, 4 * k2, v0, v1);
            }
        } else {
            int p = g - 1, a = p / 5, cc = p % 5;
            float dx = xi[a * 3 + 0] - xj[e * 15 + cc * 3 + 0];
            float dy = xi[a * 3 + 1] - xj[e * 15 + cc * 3 + 1];
            float dz = xi[a * 3 + 2] - xj[e * 15 + cc * 3 + 2];
            float d = sqrtf(dx * dx + dy * dy + dz * dz + 1e-6f);
            unsigned kb = (unsigned)(16 + p * 16) * 2;
#pragma unroll
            for (int m2 = 0; m2 < 8; m2++) {
                float mu0 = 2.0f + (float)(2 * m2) * (20.0f / 15.0f);
                float mu1 = 2.0f + (float)(2 * m2 + 1) * (20.0f / 15.0f);
                float z0 = (d - mu0) * inv_sig, z1 = (d - mu1) * inv_sig;
                split_store(rh, rl, kb + 4 * m2, __expf(-z0 * z0), __expf(-z1 * z1));
            }
        }
    }
    __syncthreads();

    // ---- mma mainloop ----
    int lrow = ((lane >> 3) & 1) * 8 + (lane & 7);
    unsigned aoff = (unsigned)lrow * FPITCH + ((unsigned)(lane >> 4)) * 16;
    unsigned ah_base = smem_base + SMB_FH + aoff;
    unsigned al_base = smem_base + SMB_FL + aoff;

    float acc[3][2][4];
#pragma unroll
    for (int m = 0; m < 3; m++)
#pragma unroll
        for (int j = 0; j < 2; j++)
#pragma unroll
            for (int q = 0; q < 4; q++) acc[m][j][q] = 0.0f;

    const uint2* bH = g_WfHi + (wid * 2) * 32 + lane;
    const uint2* bL = g_WfLo + (wid * 2) * 32 + lane;
    uint2 Bh[2], Bl[2], Bh2[2], Bl2[2];
#pragma unroll
    for (int j = 0; j < 2; j++) { Bh[j] = bH[j * 32]; Bl[j] = bL[j * 32]; }

    for (int ks = 0; ks < NKS; ks++) {
        if (ks < NKS - 1) {
#pragma unroll
            for (int j = 0; j < 2; j++) {
                Bh2[j] = bH[(ks + 1) * 512 + j * 32];
                Bl2[j] = bL[(ks + 1) * 512 + j * 32];
            }
        }
        unsigned Ah[3][4], Al[3][4];
#pragma unroll
        for (int m = 0; m < 3; m++) ldm4(Ah[m], ah_base + m * (16 * FPITCH) + ks * 32);
#pragma unroll
        for (int m = 0; m < 3; m++) ldm4(Al[m], al_base + m * (16 * FPITCH) + ks * 32);
#pragma unroll
        for (int m = 0; m < 3; m++) {
#pragma unroll
            for (int j = 0; j < 2; j++) {
                mma16816(acc[m][j], Ah[m], Bh[j]);
                mma16816(acc[m][j], Ah[m], Bl[j]);
                mma16816(acc[m][j], Al[m], Bh[j]);
            }
        }
#pragma unroll
        for (int j = 0; j < 2; j++) { Bh[j] = Bh2[j]; Bl[j] = Bl2[j]; }
    }
    __syncthreads();   // featT dead; reuse as Esh

    // write D frags to Esh[edge][ch]
    float* Esh = smf;  // [48][EPITCH] = 25.3 KB, aliases featT
    int g = lane >> 2, tg = lane & 3;
#pragma unroll
    for (int m = 0; m < 3; m++) {
#pragma unroll
        for (int j = 0; j < 2; j++) {
            int ch = (wid * 2 + j) * 8 + 2 * tg;
            int e0 = m * 16 + g;
            Esh[e0 * EPITCH + ch]            = acc[m][j][0];
            Esh[e0 * EPITCH + ch + 1]        = acc[m][j][1];
            Esh[(e0 + 8) * EPITCH + ch]      = acc[m][j][2];
            Esh[(e0 + 8) * EPITCH + ch + 1]  = acc[m][j][3];
        }
    }
    __syncthreads();

    // LayerNorm: warp w handles edges w*6 .. w*6+5
    for (int e = wid * 6; e < wid * 6 + 6; e++) {
        float v0 = Esh[e * EPITCH + lane];
        float v1 = Esh[e * EPITCH + lane + 32];
        float v2 = Esh[e * EPITCH + lane + 64];
        float v3 = Esh[e * EPITCH + lane + 96];
        float s  = v0 + v1 + v2 + v3;
        float ss = v0 * v0 + v1 * v1 + v2 * v2 + v3 * v3;
#pragma unroll
        for (int o = 16; o > 0; o >>= 1) {
            s  += __shfl_xor_sync(0xffffffffu, s, o);
            ss += __shfl_xor_sync(0xffffffffu, ss, o);
        }
        float mean = s * (1.0f / 128.0f);
        float var  = ss * (1.0f / 128.0f) - mean * mean;
        float rstd = rsqrtf(var + 1e-5f);
        size_t base = ((size_t)row * KNB + e) * 128;
        outE[base + lane]      = (v0 - mean) * rstd * ln_g[lane]      + ln_b[lane];
        outE[base + lane + 32] = (v1 - mean) * rstd * ln_g[lane + 32] + ln_b[lane + 32];
        outE[base + lane + 64] = (v2 - mean) * rstd * ln_g[lane + 64] + ln_b[lane + 64];
        outE[base + lane + 96] = (v3 - mean) * rstd * ln_g[lane + 96] + ln_b[lane + 96];
    }
}

// ---------------------------------------------------------------------------
extern "C" void kernel_launch(void* const* d_in, const int* in_sizes, int n_in,
                              void* d_out, int out_size) {
    const float* X     = (const float*)d_in[0];
    const int*   S     = (const int*)d_in[2];
    const int*   ridx  = (const int*)d_in[3];
    const int*   table = (const int*)d_in[5];
    const float* W_pos = (const float*)d_in[6];
    const float* b_pos = (const float*)d_in[7];
    const float* W_e   = (const float*)d_in[8];
    const float* ln_g  = (const float*)d_in[9];
    const float* ln_b  = (const float*)d_in[10];
    float* out = (float*)d_out;

    const size_t E_elems = (size_t)NRES * KNB * NOUT;
    int write_idx = (out_size >= (int)(E_elems + (size_t)NRES * KNB)) ? 1 : 0;

    build_xall_kernel<<<(NRES + 255) / 256, 256>>>(X, S, table);
    prep_w_kernel<<<(NKS * 16 * 32 + 255) / 256, 256>>>(W_e);
    topk_kernel<<<NRES, 256>>>(out + E_elems, write_idx);

    cudaFuncSetAttribute(edge_kernel, cudaFuncAttributeMaxDynamicSharedMemorySize, SMB_TOT);
    edge_kernel<<<NRES, 256, SMB_TOT>>>(ridx, W_pos, b_pos, ln_g, ln_b, out);
}